// round 8
// baseline (speedup 1.0000x reference)
#include <cuda_runtime.h>

#define N_NODES 50000
#define N_EDGES 200000
#define OUTD 32
#define IN_SELF 128
#define EDGE_DIM 16

// fused launch geometry: even bids < 2*EB are edge, rest are self-GEMM
#define EB 296
#define SB 391            // ceil(50000/128)
#define FUSED_BLOCKS (EB + SB)   // 687
#define FT 256

#define BN 128
#define KB 32
#define BNP 132
#define NT 256

__device__ float g_scratch[N_NODES * OUTD + N_NODES];

__device__ __forceinline__ void red_add_v4(float* ptr, float4 v) {
    asm volatile("red.global.add.v4.f32 [%0], {%1, %2, %3, %4};"
                 :: "l"(ptr), "f"(v.x), "f"(v.y), "f"(v.z), "f"(v.w)
                 : "memory");
}

__device__ __forceinline__ void fma2(unsigned long long& d,
                                     unsigned long long a,
                                     unsigned long long b) {
    asm("fma.rn.f32x2 %0, %1, %2, %0;" : "+l"(d) : "l"(a), "l"(b));
}

__device__ __forceinline__ unsigned long long packdup(float v) {
    unsigned long long r;
    asm("mov.b64 %0, {%1, %1};" : "=l"(r) : "f"(v));
    return r;
}

// ---------------------------------------------------------------------------
// Fused kernel: block-specialized.
//   edge blocks: scatter messages into g_scratch (atomics; LSU/L2-bound)
//   self blocks: out[n,c] = h_self[n,:] . W_self[c,:]  (raw, no relu; FMA-bound)
// Interleaved bid mapping keeps both flavors co-resident per wave.
// ---------------------------------------------------------------------------
__global__ void __launch_bounds__(FT, 3)
fused_kernel(const float* __restrict__ h_neigh,
             const float* __restrict__ h_self,
             const float* __restrict__ edge_features,
             const float* __restrict__ W_edge,
             const float* __restrict__ b_edge,
             const float* __restrict__ W_self,
             const int* __restrict__ src,
             const int* __restrict__ dst,
             float* __restrict__ out) {
    const int bid = blockIdx.x;
    const bool is_edge = (bid < 2 * EB) && ((bid & 1) == 0);
    const int t = threadIdx.x;

    if (is_edge) {
        // =================== EDGE PATH ===================
        __shared__ __align__(16) float sW[EDGE_DIM * OUTD];
        __shared__ __align__(16) float sb[OUTD];
        #pragma unroll
        for (int idx = t; idx < OUTD * EDGE_DIM; idx += FT) {
            int j = idx >> 4, k = idx & 15;
            float s = 0.f;
            #pragma unroll
            for (int i = 0; i < OUTD; i++)
                s += W_edge[(i * OUTD + j) * EDGE_DIM + k];
            sW[k * OUTD + j] = s;
        }
        if (t < OUTD) {
            float s2 = 0.f;
            #pragma unroll
            for (int i = 0; i < OUTD; i++)
                s2 += b_edge[i * OUTD + t];
            sb[t] = s2;
        }
        __syncthreads();

        float* g_agg = g_scratch;
        float* g_deg = g_scratch + N_NODES * OUTD;

        const int eid = bid >> 1;          // 0..EB-1
        const int lane = t & 31;
        const int warp = t >> 5;
        const int g = lane >> 3;
        const int p = lane & 7;
        const int wpb = FT >> 5;           // 8
        const int nwarps = EB * wpb;       // 2368
        const int NGROUPS = N_EDGES / 4;   // 50000

        for (int grp = eid * wpb + warp; grp < NGROUPS; grp += nwarps) {
            int e0 = grp * 4;
            int e = e0 + g;
            int s = src[e];
            int d = dst[e];

            float2 ef = *reinterpret_cast<const float2*>(
                &edge_features[e0 * EDGE_DIM + lane * 2]);

            float4 acc = *reinterpret_cast<const float4*>(&sb[4 * p]);
            #pragma unroll
            for (int k = 0; k < EDGE_DIM; k++) {
                float ek = __shfl_sync(0xffffffffu, (k & 1) ? ef.y : ef.x, k >> 1, 8);
                float4 w = *reinterpret_cast<const float4*>(&sW[k * OUTD + 4 * p]);
                acc.x = fmaf(ek, w.x, acc.x);
                acc.y = fmaf(ek, w.y, acc.y);
                acc.z = fmaf(ek, w.z, acc.z);
                acc.w = fmaf(ek, w.w, acc.w);
            }

            float4 hv = *reinterpret_cast<const float4*>(&h_neigh[s * OUTD + 4 * p]);
            float4 msg = make_float4(hv.x * acc.x, hv.y * acc.y,
                                     hv.z * acc.z, hv.w * acc.w);
            red_add_v4(&g_agg[d * OUTD + 4 * p], msg);
            if (p == 0) atomicAdd(&g_deg[d], 1.0f);
        }
        return;
    }

    // =================== SELF-GEMM PATH ===================
    // sid in [0, SB): odd bids<592 -> bid>>1; bids>=592 -> bid-EB
    const int sid = (bid < 2 * EB) ? (bid >> 1) : (bid - EB);

    __shared__ __align__(16) float h_s[2][KB][BNP];
    __shared__ __align__(16) float w_s[2][KB][OUTD];

    const int nbase = sid * BN;
    const int kg = t >> 7;
    const int t1 = t & 127;
    const int tn = t1 >> 3;
    const int tc = t1 & 7;
    const int ko = kg * (KB / 2);

    const int snode = t >> 3;
    const int skvec = t & 7;
    const int wchan = t >> 3;
    const int wkvec = t & 7;

    float4 hreg[4];
    float4 wreg;

    auto load_regs = [&](int kc) {
        #pragma unroll
        for (int i = 0; i < 4; i++) {
            int node = snode + i * (NT >> 3);
            int gn = nbase + node;
            float4 v = make_float4(0.f, 0.f, 0.f, 0.f);
            if (gn < N_NODES)
                v = *reinterpret_cast<const float4*>(
                    &h_self[gn * IN_SELF + kc * KB + skvec * 4]);
            hreg[i] = v;
        }
        wreg = *reinterpret_cast<const float4*>(
            &W_self[wchan * IN_SELF + kc * KB + wkvec * 4]);
    };

    auto store_smem = [&](int b) {
        #pragma unroll
        for (int i = 0; i < 4; i++) {
            int node = snode + i * (NT >> 3);
            h_s[b][skvec * 4 + 0][node] = hreg[i].x;
            h_s[b][skvec * 4 + 1][node] = hreg[i].y;
            h_s[b][skvec * 4 + 2][node] = hreg[i].z;
            h_s[b][skvec * 4 + 3][node] = hreg[i].w;
        }
        w_s[b][wkvec * 4 + 0][wchan] = wreg.x;
        w_s[b][wkvec * 4 + 1][wchan] = wreg.y;
        w_s[b][wkvec * 4 + 2][wchan] = wreg.z;
        w_s[b][wkvec * 4 + 3][wchan] = wreg.w;
    };

    unsigned long long acc2[4][4];
    #pragma unroll
    for (int p = 0; p < 4; p++)
        #pragma unroll
        for (int c = 0; c < 4; c++) acc2[p][c] = 0ull;

    load_regs(0);
    store_smem(0);
    __syncthreads();

    #pragma unroll
    for (int kc = 0; kc < 4; kc++) {
        int b = kc & 1;
        if (kc < 3) load_regs(kc + 1);
        #pragma unroll
        for (int kk = 0; kk < KB / 2; kk++) {
            int k = kk + ko;
            float4 w = *reinterpret_cast<const float4*>(&w_s[b][k][tc * 4]);
            unsigned long long w0 = packdup(w.x);
            unsigned long long w1 = packdup(w.y);
            unsigned long long w2 = packdup(w.z);
            unsigned long long w3 = packdup(w.w);
            ulonglong2 hA = *reinterpret_cast<const ulonglong2*>(&h_s[b][k][tn * 8]);
            ulonglong2 hB = *reinterpret_cast<const ulonglong2*>(&h_s[b][k][tn * 8 + 4]);

            fma2(acc2[0][0], hA.x, w0);
            fma2(acc2[0][1], hA.x, w1);
            fma2(acc2[0][2], hA.x, w2);
            fma2(acc2[0][3], hA.x, w3);
            fma2(acc2[1][0], hA.y, w0);
            fma2(acc2[1][1], hA.y, w1);
            fma2(acc2[1][2], hA.y, w2);
            fma2(acc2[1][3], hA.y, w3);
            fma2(acc2[2][0], hB.x, w0);
            fma2(acc2[2][1], hB.x, w1);
            fma2(acc2[2][2], hB.x, w2);
            fma2(acc2[2][3], hB.x, w3);
            fma2(acc2[3][0], hB.y, w0);
            fma2(acc2[3][1], hB.y, w1);
            fma2(acc2[3][2], hB.y, w2);
            fma2(acc2[3][3], hB.y, w3);
        }
        if (kc < 3) store_smem(1 - b);
        __syncthreads();
    }

    // cross-group reduce through smem; write raw self sums to out (no relu)
    unsigned long long* red = reinterpret_cast<unsigned long long*>(h_s);
    if (kg == 1) {
        #pragma unroll
        for (int p = 0; p < 4; p++)
            #pragma unroll
            for (int c = 0; c < 4; c++)
                red[t1 * 16 + p * 4 + c] = acc2[p][c];
    }
    __syncthreads();
    if (kg == 0) {
        #pragma unroll
        for (int p = 0; p < 4; p++) {
            float lo[4], hi[4];
            #pragma unroll
            for (int c = 0; c < 4; c++) {
                float2 a = *reinterpret_cast<float2*>(&acc2[p][c]);
                unsigned long long o = red[t1 * 16 + p * 4 + c];
                float2 bq = *reinterpret_cast<float2*>(&o);
                lo[c] = a.x + bq.x;
                hi[c] = a.y + bq.y;
            }
            int gn0 = nbase + tn * 8 + 2 * p;
            if (gn0 < N_NODES)
                *reinterpret_cast<float4*>(&out[gn0 * OUTD + tc * 4]) =
                    make_float4(lo[0], lo[1], lo[2], lo[3]);
            if (gn0 + 1 < N_NODES)
                *reinterpret_cast<float4*>(&out[(gn0 + 1) * OUTD + tc * 4]) =
                    make_float4(hi[0], hi[1], hi[2], hi[3]);
        }
    }
}

// ---------------------------------------------------------------------------
// Finish kernel: out[n,c] = relu( out[n,c] + (agg[n,:]/max(deg,1)) . W_neigh[c,:] )
// One staged K=32 chunk per 128-node tile; 4 nodes x 4 chans per thread.
// ---------------------------------------------------------------------------
__global__ void __launch_bounds__(NT, 3)
finish_kernel(const float* __restrict__ W_neigh,
              float* __restrict__ out) {
    __shared__ __align__(16) float a_s[KB][BNP];
    __shared__ __align__(16) float w_s[KB][OUTD];
    __shared__ float sinv[BN];

    const float* g_agg = g_scratch;
    const float* g_deg = g_scratch + N_NODES * OUTD;

    const int t = threadIdx.x;
    const int nbase = blockIdx.x * BN;
    const int tn = t >> 3;      // 0..31 node quad
    const int tc = t & 7;       // channel quad

    if (t < BN) {
        int gn = nbase + t;
        sinv[t] = (gn < N_NODES) ? 1.0f / fmaxf(g_deg[gn], 1.0f) : 0.f;
    }
    __syncthreads();

    // stage normalized agg transposed: idx = t + i*NT, node=idx>>3, kvec=idx&7
    #pragma unroll
    for (int i = 0; i < 4; i++) {
        int idx = t + i * NT;
        int node = idx >> 3;
        int kvec = idx & 7;
        int gn = nbase + node;
        float4 v = make_float4(0.f, 0.f, 0.f, 0.f);
        if (gn < N_NODES) {
            v = *reinterpret_cast<const float4*>(&g_agg[gn * OUTD + kvec * 4]);
            float iv = sinv[node];
            v.x *= iv; v.y *= iv; v.z *= iv; v.w *= iv;
        }
        a_s[kvec * 4 + 0][node] = v.x;
        a_s[kvec * 4 + 1][node] = v.y;
        a_s[kvec * 4 + 2][node] = v.z;
        a_s[kvec * 4 + 3][node] = v.w;
    }
    // stage W_neigh transposed
    {
        int chan = t >> 3, kvec = t & 7;
        float4 w = *reinterpret_cast<const float4*>(&W_neigh[chan * OUTD + kvec * 4]);
        w_s[kvec * 4 + 0][chan] = w.x;
        w_s[kvec * 4 + 1][chan] = w.y;
        w_s[kvec * 4 + 2][chan] = w.z;
        w_s[kvec * 4 + 3][chan] = w.w;
    }
    __syncthreads();

    // init acc with self part already in out
    float acc[4][4];
    #pragma unroll
    for (int r = 0; r < 4; r++) {
        int gn = nbase + tn * 4 + r;
        float4 s = make_float4(0.f, 0.f, 0.f, 0.f);
        if (gn < N_NODES)
            s = *reinterpret_cast<const float4*>(&out[gn * OUTD + tc * 4]);
        acc[r][0] = s.x; acc[r][1] = s.y; acc[r][2] = s.z; acc[r][3] = s.w;
    }

    #pragma unroll
    for (int kk = 0; kk < KB; kk++) {
        float4 w = *reinterpret_cast<const float4*>(&w_s[kk][tc * 4]);
        float4 h = *reinterpret_cast<const float4*>(&a_s[kk][tn * 4]);
        float hr[4] = {h.x, h.y, h.z, h.w};
        float wc[4] = {w.x, w.y, w.z, w.w};
        #pragma unroll
        for (int r = 0; r < 4; r++)
            #pragma unroll
            for (int c = 0; c < 4; c++)
                acc[r][c] = fmaf(hr[r], wc[c], acc[r][c]);
    }

    #pragma unroll
    for (int r = 0; r < 4; r++) {
        int gn = nbase + tn * 4 + r;
        if (gn < N_NODES) {
            float4 o = make_float4(fmaxf(acc[r][0], 0.f), fmaxf(acc[r][1], 0.f),
                                   fmaxf(acc[r][2], 0.f), fmaxf(acc[r][3], 0.f));
            *reinterpret_cast<float4*>(&out[gn * OUTD + tc * 4]) = o;
        }
    }
}

extern "C" void kernel_launch(void* const* d_in, const int* in_sizes, int n_in,
                              void* d_out, int out_size) {
    const float* h_neigh       = (const float*)d_in[0];
    const float* h_self        = (const float*)d_in[1];
    const float* edge_features = (const float*)d_in[2];
    const float* W_edge        = (const float*)d_in[3];
    const float* b_edge        = (const float*)d_in[4];
    const float* W_self        = (const float*)d_in[5];
    const float* W_neigh       = (const float*)d_in[6];
    const int*   src           = (const int*)d_in[7];
    const int*   dst           = (const int*)d_in[8];
    float* out = (float*)d_out;

    void* scratch_ptr = nullptr;
    cudaGetSymbolAddress(&scratch_ptr, g_scratch);
    cudaMemsetAsync(scratch_ptr, 0, sizeof(float) * (N_NODES * OUTD + N_NODES), 0);

    fused_kernel<<<FUSED_BLOCKS, FT>>>(h_neigh, h_self, edge_features,
                                       W_edge, b_edge, W_self, src, dst, out);
    finish_kernel<<<SB, NT>>>(W_neigh, out);
}